// round 7
// baseline (speedup 1.0000x reference)
#include <cuda_runtime.h>
#include <cuda_fp16.h>

#define N_NODES 16384
#define SZ 128
typedef unsigned long long ull;

// ---------------- f32x2 packed helpers (sm_103a) ----------------
__device__ __forceinline__ ull ffma2(ull a, ull b, ull c) {
    ull d;
    asm("fma.rn.f32x2 %0, %1, %2, %3;" : "=l"(d) : "l"(a), "l"(b), "l"(c));
    return d;
}
__device__ __forceinline__ ull pack2(float x, float y) {
    ull d;
    asm("mov.b64 %0, {%1, %2};" : "=l"(d) : "f"(x), "f"(y));
    return d;
}
__device__ __forceinline__ float2 unpack2(ull v) {
    float2 r;
    asm("mov.b64 {%0, %1}, %2;" : "=f"(r.x), "=f"(r.y) : "l"(v));
    return r;
}
__device__ __forceinline__ unsigned h2u(__half2 h) { return *(unsigned*)&h; }

// ---------------- scratch ----------------
__device__ float  g_h1[N_NODES * SZ];
__device__ float  g_h2[N_NODES * SZ];
__device__ float  g_msg[N_NODES * SZ];
__device__ float  g_q[N_NODES * SZ];
__device__ __half g_mk[N_NODES * SZ];
__device__ __half g_mv[N_NODES * SZ];
__device__ float  g_att[N_NODES * SZ];

// ---------------- GEMM v3: C[N,128]=f(A@W+b)(+add); FFMA2, zero packs ------
// BM=32, BN=128, BK=32, 128 threads; thread: 4 rows x 8 cols (4 col-pairs).
// A tile stored DUPLICATED (a,a) as ull -> b64 broadcast loads, no packs.
template <int RELU_IN, int RELU_OUT, int HAS_BIAS, int HAS_ADD>
__global__ __launch_bounds__(128) void gemm128(
    const float* __restrict__ A, const float* __restrict__ W,
    const float* __restrict__ bias, const float* __restrict__ add,
    float* __restrict__ C)
{
    __shared__ __align__(16) ull   As2[32 * 32];   // [k][row] dup pairs, 8KB
    __shared__ __align__(16) float Ws[32 * 128];   // [k][col], 16KB
    const int t = threadIdx.x;
    const int tx = t & 15;          // col octet: cols tx*8 .. tx*8+7
    const int ty = t >> 4;          // row quad:  rows ty*4 .. ty*4+3
    const int row0 = blockIdx.x * 32;

    ull acc[4][4];
#pragma unroll
    for (int r = 0; r < 4; r++)
#pragma unroll
        for (int c = 0; c < 4; c++) acc[r][c] = 0ull;

    for (int kt = 0; kt < 4; kt++) {
        const int kk0 = kt * 32;
        __syncthreads();
        // A tile 32x32 -> transposed duplicated [k][row]
#pragma unroll
        for (int i = 0; i < 2; i++) {
            int f = t + i * 128;
            int r = f >> 3, c4 = f & 7;
            float4 v = *(const float4*)(A + (row0 + r) * 128 + kk0 + c4 * 4);
            if (RELU_IN) {
                v.x = fmaxf(v.x, 0.f); v.y = fmaxf(v.y, 0.f);
                v.z = fmaxf(v.z, 0.f); v.w = fmaxf(v.w, 0.f);
            }
            As2[(c4 * 4 + 0) * 32 + r] = pack2(v.x, v.x);
            As2[(c4 * 4 + 1) * 32 + r] = pack2(v.y, v.y);
            As2[(c4 * 4 + 2) * 32 + r] = pack2(v.z, v.z);
            As2[(c4 * 4 + 3) * 32 + r] = pack2(v.w, v.w);
        }
        // W tile 32x128
#pragma unroll
        for (int i = 0; i < 8; i++) {
            int f = t + i * 128;
            int kr = f >> 5, c4 = f & 31;
            *(float4*)(Ws + kr * 128 + c4 * 4) =
                *(const float4*)(W + (kk0 + kr) * 128 + c4 * 4);
        }
        __syncthreads();
#pragma unroll
        for (int kk = 0; kk < 32; kk++) {
            ulonglong2 a01 = *(const ulonglong2*)(As2 + kk * 32 + ty * 4);
            ulonglong2 a23 = *(const ulonglong2*)(As2 + kk * 32 + ty * 4 + 2);
            ulonglong2 w01 = *(const ulonglong2*)(Ws + kk * 128 + tx * 8);
            ulonglong2 w23 = *(const ulonglong2*)(Ws + kk * 128 + tx * 8 + 4);
            acc[0][0] = ffma2(a01.x, w01.x, acc[0][0]);
            acc[0][1] = ffma2(a01.x, w01.y, acc[0][1]);
            acc[0][2] = ffma2(a01.x, w23.x, acc[0][2]);
            acc[0][3] = ffma2(a01.x, w23.y, acc[0][3]);
            acc[1][0] = ffma2(a01.y, w01.x, acc[1][0]);
            acc[1][1] = ffma2(a01.y, w01.y, acc[1][1]);
            acc[1][2] = ffma2(a01.y, w23.x, acc[1][2]);
            acc[1][3] = ffma2(a01.y, w23.y, acc[1][3]);
            acc[2][0] = ffma2(a23.x, w01.x, acc[2][0]);
            acc[2][1] = ffma2(a23.x, w01.y, acc[2][1]);
            acc[2][2] = ffma2(a23.x, w23.x, acc[2][2]);
            acc[2][3] = ffma2(a23.x, w23.y, acc[2][3]);
            acc[3][0] = ffma2(a23.y, w01.x, acc[3][0]);
            acc[3][1] = ffma2(a23.y, w01.y, acc[3][1]);
            acc[3][2] = ffma2(a23.y, w23.x, acc[3][2]);
            acc[3][3] = ffma2(a23.y, w23.y, acc[3][3]);
        }
    }

    float4 bz0 = make_float4(0.f, 0.f, 0.f, 0.f), bz1 = bz0;
    if (HAS_BIAS) {
        bz0 = *(const float4*)(bias + tx * 8);
        bz1 = *(const float4*)(bias + tx * 8 + 4);
    }
#pragma unroll
    for (int r = 0; r < 4; r++) {
        int gr = row0 + ty * 4 + r;
        float2 c0 = unpack2(acc[r][0]), c1 = unpack2(acc[r][1]);
        float2 c2 = unpack2(acc[r][2]), c3 = unpack2(acc[r][3]);
        float4 o0 = make_float4(c0.x + bz0.x, c0.y + bz0.y, c1.x + bz0.z, c1.y + bz0.w);
        float4 o1 = make_float4(c2.x + bz1.x, c2.y + bz1.y, c3.x + bz1.z, c3.y + bz1.w);
        if (RELU_OUT) {
            o0.x = fmaxf(o0.x, 0.f); o0.y = fmaxf(o0.y, 0.f);
            o0.z = fmaxf(o0.z, 0.f); o0.w = fmaxf(o0.w, 0.f);
            o1.x = fmaxf(o1.x, 0.f); o1.y = fmaxf(o1.y, 0.f);
            o1.z = fmaxf(o1.z, 0.f); o1.w = fmaxf(o1.w, 0.f);
        }
        if (HAS_ADD) {
            float4 a0 = *(const float4*)(add + gr * 128 + tx * 8);
            float4 a1 = *(const float4*)(add + gr * 128 + tx * 8 + 4);
            o0.x += a0.x; o0.y += a0.y; o0.z += a0.z; o0.w += a0.w;
            o1.x += a1.x; o1.y += a1.y; o1.z += a1.z; o1.w += a1.w;
        }
        *(float4*)(C + gr * 128 + tx * 8) = o0;
        *(float4*)(C + gr * 128 + tx * 8 + 4) = o1;
    }
}

// ---------------- dual GEMM -> fp16 outputs: mk = A@W1, mv = A@W2 ----------
__global__ __launch_bounds__(128) void gemm128_dual_h(
    const float* __restrict__ A, const float* __restrict__ W1g,
    const float* __restrict__ W2g, __half* __restrict__ C1,
    __half* __restrict__ C2)
{
    __shared__ __align__(16) ull   As2[32 * 32];
    __shared__ __align__(16) float Ws1[32 * 128];
    __shared__ __align__(16) float Ws2[32 * 128];
    const int t = threadIdx.x;
    const int tx = t & 15;
    const int ty = t >> 4;
    const int row0 = blockIdx.x * 32;

    ull a1[4][4], a2[4][4];
#pragma unroll
    for (int r = 0; r < 4; r++)
#pragma unroll
        for (int c = 0; c < 4; c++) { a1[r][c] = 0ull; a2[r][c] = 0ull; }

    for (int kt = 0; kt < 4; kt++) {
        const int kk0 = kt * 32;
        __syncthreads();
#pragma unroll
        for (int i = 0; i < 2; i++) {
            int f = t + i * 128;
            int r = f >> 3, c4 = f & 7;
            float4 v = *(const float4*)(A + (row0 + r) * 128 + kk0 + c4 * 4);
            As2[(c4 * 4 + 0) * 32 + r] = pack2(v.x, v.x);
            As2[(c4 * 4 + 1) * 32 + r] = pack2(v.y, v.y);
            As2[(c4 * 4 + 2) * 32 + r] = pack2(v.z, v.z);
            As2[(c4 * 4 + 3) * 32 + r] = pack2(v.w, v.w);
        }
#pragma unroll
        for (int i = 0; i < 8; i++) {
            int f = t + i * 128;
            int kr = f >> 5, c4 = f & 31;
            *(float4*)(Ws1 + kr * 128 + c4 * 4) =
                *(const float4*)(W1g + (kk0 + kr) * 128 + c4 * 4);
            *(float4*)(Ws2 + kr * 128 + c4 * 4) =
                *(const float4*)(W2g + (kk0 + kr) * 128 + c4 * 4);
        }
        __syncthreads();
#pragma unroll
        for (int kk = 0; kk < 32; kk++) {
            ulonglong2 a01 = *(const ulonglong2*)(As2 + kk * 32 + ty * 4);
            ulonglong2 a23 = *(const ulonglong2*)(As2 + kk * 32 + ty * 4 + 2);
            {
                ulonglong2 w01 = *(const ulonglong2*)(Ws1 + kk * 128 + tx * 8);
                ulonglong2 w23 = *(const ulonglong2*)(Ws1 + kk * 128 + tx * 8 + 4);
                a1[0][0] = ffma2(a01.x, w01.x, a1[0][0]);
                a1[0][1] = ffma2(a01.x, w01.y, a1[0][1]);
                a1[0][2] = ffma2(a01.x, w23.x, a1[0][2]);
                a1[0][3] = ffma2(a01.x, w23.y, a1[0][3]);
                a1[1][0] = ffma2(a01.y, w01.x, a1[1][0]);
                a1[1][1] = ffma2(a01.y, w01.y, a1[1][1]);
                a1[1][2] = ffma2(a01.y, w23.x, a1[1][2]);
                a1[1][3] = ffma2(a01.y, w23.y, a1[1][3]);
                a1[2][0] = ffma2(a23.x, w01.x, a1[2][0]);
                a1[2][1] = ffma2(a23.x, w01.y, a1[2][1]);
                a1[2][2] = ffma2(a23.x, w23.x, a1[2][2]);
                a1[2][3] = ffma2(a23.x, w23.y, a1[2][3]);
                a1[3][0] = ffma2(a23.y, w01.x, a1[3][0]);
                a1[3][1] = ffma2(a23.y, w01.y, a1[3][1]);
                a1[3][2] = ffma2(a23.y, w23.x, a1[3][2]);
                a1[3][3] = ffma2(a23.y, w23.y, a1[3][3]);
            }
            {
                ulonglong2 w01 = *(const ulonglong2*)(Ws2 + kk * 128 + tx * 8);
                ulonglong2 w23 = *(const ulonglong2*)(Ws2 + kk * 128 + tx * 8 + 4);
                a2[0][0] = ffma2(a01.x, w01.x, a2[0][0]);
                a2[0][1] = ffma2(a01.x, w01.y, a2[0][1]);
                a2[0][2] = ffma2(a01.x, w23.x, a2[0][2]);
                a2[0][3] = ffma2(a01.x, w23.y, a2[0][3]);
                a2[1][0] = ffma2(a01.y, w01.x, a2[1][0]);
                a2[1][1] = ffma2(a01.y, w01.y, a2[1][1]);
                a2[1][2] = ffma2(a01.y, w23.x, a2[1][2]);
                a2[1][3] = ffma2(a01.y, w23.y, a2[1][3]);
                a2[2][0] = ffma2(a23.x, w01.x, a2[2][0]);
                a2[2][1] = ffma2(a23.x, w01.y, a2[2][1]);
                a2[2][2] = ffma2(a23.x, w23.x, a2[2][2]);
                a2[2][3] = ffma2(a23.x, w23.y, a2[2][3]);
                a2[3][0] = ffma2(a23.y, w01.x, a2[3][0]);
                a2[3][1] = ffma2(a23.y, w01.y, a2[3][1]);
                a2[3][2] = ffma2(a23.y, w23.x, a2[3][2]);
                a2[3][3] = ffma2(a23.y, w23.y, a2[3][3]);
            }
        }
    }
#pragma unroll
    for (int r = 0; r < 4; r++) {
        int gr = row0 + ty * 4 + r;
        {
            float2 c0 = unpack2(a1[r][0]), c1 = unpack2(a1[r][1]);
            float2 c2 = unpack2(a1[r][2]), c3 = unpack2(a1[r][3]);
            uint4 o;
            o.x = h2u(__float22half2_rn(c0));
            o.y = h2u(__float22half2_rn(c1));
            o.z = h2u(__float22half2_rn(c2));
            o.w = h2u(__float22half2_rn(c3));
            *(uint4*)(C1 + (long)gr * 128 + tx * 8) = o;
        }
        {
            float2 c0 = unpack2(a2[r][0]), c1 = unpack2(a2[r][1]);
            float2 c2 = unpack2(a2[r][2]), c3 = unpack2(a2[r][3]);
            uint4 o;
            o.x = h2u(__float22half2_rn(c0));
            o.y = h2u(__float22half2_rn(c1));
            o.z = h2u(__float22half2_rn(c2));
            o.w = h2u(__float22half2_rn(c3));
            *(uint4*)(C2 + (long)gr * 128 + tx * 8) = o;
        }
    }
}

// ---------------- attention: 1 warp/node, fp16 gather tables ----------------
struct __align__(16) WarpSmem {
    float dist[32 * 36];   // [k][d] pad-36
    float seq[32 * 20];    // [k][s] pad-20
    float ud[8 * 32];
    float us[8 * 16];
    float c0[8];
    float lgk[32 * 10];    // [k][h] pad-10
    float sd[8 * 32];
    float ss[8 * 16];
    int   jb[32];
};

__global__ __launch_bounds__(128) void attn_kernel(
    const float* __restrict__ dist_g, const float* __restrict__ seq_g,
    const int* __restrict__ idx, const float* __restrict__ qg,
    const __half* __restrict__ mkh, const __half* __restrict__ mvh,
    const float* __restrict__ Wk, const float* __restrict__ bk,
    const float* __restrict__ Wv, const float* __restrict__ bv,
    float* __restrict__ att_out)
{
    __shared__ WarpSmem S[4];
    const int lane = threadIdx.x & 31;
    const int w = threadIdx.x >> 5;
    WarpSmem& s = S[w];
    const int n = blockIdx.x * 4 + w;

    // ---- Phase A: coalesced staging
    const float4 qv = ((const float4*)(qg + (long)n * 128))[lane];
    s.jb[lane] = idx[n * 32 + lane];
    {
        const float4* dg = (const float4*)(dist_g + (long)n * 1024);
#pragma unroll
        for (int it = 0; it < 8; it++) {
            int i4 = it * 32 + lane;
            float4 v = dg[i4];
            float* p = s.dist + (i4 >> 3) * 36 + (i4 & 7) * 4;
            p[0] = v.x; p[1] = v.y; p[2] = v.z; p[3] = v.w;
        }
        const float4* sg = (const float4*)(seq_g + (long)n * 512);
#pragma unroll
        for (int it = 0; it < 4; it++) {
            int i4 = it * 32 + lane;
            float4 v = sg[i4];
            float* p = s.seq + (i4 >> 2) * 20 + (i4 & 3) * 4;
            p[0] = v.x; p[1] = v.y; p[2] = v.z; p[3] = v.w;
        }
    }
    __syncwarp();

    // ---- Phase B: folds ud/us/c0 (Wk rows are L1-resident)
    const int h4 = lane >> 2;
#pragma unroll 8
    for (int r = 0; r < 48; r++) {
        float4 wv = *(const float4*)(Wk + (long)(128 + r) * 128 + lane * 4);
        float p = wv.x * qv.x + wv.y * qv.y + wv.z * qv.z + wv.w * qv.w;
        p += __shfl_xor_sync(~0u, p, 1);
        p += __shfl_xor_sync(~0u, p, 2);
        if ((lane & 3) == 0) {
            if (r < 32) s.ud[h4 * 32 + r] = p;
            else        s.us[h4 * 16 + (r - 32)] = p;
        }
    }
    {
        float4 wv = *(const float4*)(bk + lane * 4);
        float p = wv.x * qv.x + wv.y * qv.y + wv.z * qv.z + wv.w * qv.w;
        p += __shfl_xor_sync(~0u, p, 1);
        p += __shfl_xor_sync(~0u, p, 2);
        if ((lane & 3) == 0) s.c0[h4] = p;
    }
    __syncwarp();

    // ---- Phase C1: q . mk[jb[k]] — fp16 rows, 8B/lane coalesced
#pragma unroll 8
    for (int k = 0; k < 32; k++) {
        int j = s.jb[k];
        uint2 mr = *(const uint2*)(mkh + (long)j * 128 + lane * 4);
        float2 f0 = __half22float2(*(__half2*)&mr.x);
        float2 f1 = __half22float2(*(__half2*)&mr.y);
        float p = f0.x * qv.x + f0.y * qv.y + f1.x * qv.z + f1.y * qv.w;
        p += __shfl_xor_sync(~0u, p, 1);
        p += __shfl_xor_sync(~0u, p, 2);
        if ((lane & 3) == 0) s.lgk[k * 10 + h4] = p;
    }
    __syncwarp();

    // ---- Phase C2: dist/seq logit terms (lane = k) + softmax
    float lg[8];
    {
        ull dr2[16], sq2[8];
#pragma unroll
        for (int i = 0; i < 8; i++) {
            ulonglong2 v = ((const ulonglong2*)(s.dist + lane * 36))[i];
            dr2[2 * i] = v.x; dr2[2 * i + 1] = v.y;
        }
#pragma unroll
        for (int i = 0; i < 4; i++) {
            ulonglong2 v = ((const ulonglong2*)(s.seq + lane * 20))[i];
            sq2[2 * i] = v.x; sq2[2 * i + 1] = v.y;
        }
#pragma unroll
        for (int h = 0; h < 8; h++) {
            ull acc2 = 0ull;
#pragma unroll
            for (int i = 0; i < 8; i++) {
                ulonglong2 u = ((const ulonglong2*)(s.ud + h * 32))[i];
                acc2 = ffma2(dr2[2 * i], u.x, acc2);
                acc2 = ffma2(dr2[2 * i + 1], u.y, acc2);
            }
#pragma unroll
            for (int i = 0; i < 4; i++) {
                ulonglong2 u = ((const ulonglong2*)(s.us + h * 16))[i];
                acc2 = ffma2(sq2[2 * i], u.x, acc2);
                acc2 = ffma2(sq2[2 * i + 1], u.y, acc2);
            }
            float2 p = unpack2(acc2);
            lg[h] = 0.25f * (s.lgk[lane * 10 + h] + p.x + p.y + s.c0[h]);
        }
    }
#pragma unroll
    for (int h = 0; h < 8; h++) {
        float m = lg[h];
#pragma unroll
        for (int o = 16; o > 0; o >>= 1) m = fmaxf(m, __shfl_xor_sync(~0u, m, o));
        float e = __expf(lg[h] - m);
        float sm = e;
#pragma unroll
        for (int o = 16; o > 0; o >>= 1) sm += __shfl_xor_sync(~0u, sm, o);
        s.lgk[lane * 10 + h] = e / sm;
    }
    __syncwarp();

    // ---- Phase D: weighted sums — fp16 mv gather, 8B/lane
    const int sidx = lane & 15;
    float4 acc = make_float4(0.f, 0.f, 0.f, 0.f);
    ull sdl2[4] = {0ull, 0ull, 0ull, 0ull};
    float ssl[4] = {0.f, 0.f, 0.f, 0.f};
#pragma unroll 4
    for (int k = 0; k < 32; k++) {
        int j = s.jb[k];
        float a = s.lgk[k * 10 + h4];
        uint2 mr = *(const uint2*)(mvh + (long)j * 128 + lane * 4);
        float2 f0 = __half22float2(*(__half2*)&mr.x);
        float2 f1 = __half22float2(*(__half2*)&mr.y);
        acc.x += a * f0.x; acc.y += a * f0.y;
        acc.z += a * f1.x; acc.w += a * f1.y;
        float dv = s.dist[k * 36 + lane];
        ull dv2 = pack2(dv, dv);
        const ull* ap = (const ull*)(s.lgk + k * 10);
#pragma unroll
        for (int r = 0; r < 4; r++) sdl2[r] = ffma2(ap[r], dv2, sdl2[r]);
        float sv = s.seq[k * 20 + sidx];
#pragma unroll
        for (int r = 0; r < 4; r++) {
            int h2 = (lane >> 4) + 2 * r;
            ssl[r] += s.lgk[k * 10 + h2] * sv;
        }
    }
#pragma unroll
    for (int r = 0; r < 4; r++) {
        float2 p = unpack2(sdl2[r]);
        s.sd[(2 * r) * 32 + lane] = p.x;
        s.sd[(2 * r + 1) * 32 + lane] = p.y;
    }
#pragma unroll
    for (int r = 0; r < 4; r++) s.ss[lane + 32 * r] = ssl[r];
    __syncwarp();

    // ---- Phase D2: outv = acc + sd @ WvD + ss @ WvS + bv (f32x2)
    {
        const int i0 = lane * 4;
        float4 bvv = *(const float4*)(bv + i0);
        ull o01 = pack2(bvv.x + acc.x, bvv.y + acc.y);
        ull o23 = pack2(bvv.z + acc.z, bvv.w + acc.w);
#pragma unroll 8
        for (int d = 0; d < 32; d++) {
            float sdv = s.sd[h4 * 32 + d];
            ull s2 = pack2(sdv, sdv);
            ulonglong2 wv = *(const ulonglong2*)(Wv + (long)(128 + d) * 128 + i0);
            o01 = ffma2(wv.x, s2, o01);
            o23 = ffma2(wv.y, s2, o23);
        }
#pragma unroll 8
        for (int j = 0; j < 16; j++) {
            float ssv = s.ss[h4 * 16 + j];
            ull s2 = pack2(ssv, ssv);
            ulonglong2 wv = *(const ulonglong2*)(Wv + (long)(160 + j) * 128 + i0);
            o01 = ffma2(wv.x, s2, o01);
            o23 = ffma2(wv.y, s2, o23);
        }
        float2 p0 = unpack2(o01), p1 = unpack2(o23);
        *(float4*)(att_out + (long)n * 128 + i0) =
            make_float4(p0.x, p0.y, p1.x, p1.y);
    }
}

// ---------------- launch ----------------
extern "C" void kernel_launch(void* const* d_in, const int* in_sizes, int n_in,
                              void* d_out, int out_size)
{
    const float* features = (const float*)d_in[0];
    const float* distances = (const float*)d_in[1];
    const float* sequence = (const float*)d_in[2];
    const float* encoder = (const float*)d_in[3];
    const int*   idx = (const int*)d_in[4];
    const float* W1 = (const float*)d_in[5];
    const float* b1 = (const float*)d_in[6];
    const float* W2 = (const float*)d_in[7];
    const float* b2 = (const float*)d_in[8];
    const float* W3 = (const float*)d_in[9];
    const float* b3 = (const float*)d_in[10];
    const float* Wq = (const float*)d_in[11];
    const float* bq = (const float*)d_in[12];
    const float* Wk = (const float*)d_in[13];
    const float* bk = (const float*)d_in[14];
    const float* Wv = (const float*)d_in[15];
    const float* bv = (const float*)d_in[16];
    const float* Wo = (const float*)d_in[17];
    const float* bo = (const float*)d_in[18];

    float *h1, *h2, *msg, *q, *att;
    __half *mk, *mv;
    cudaGetSymbolAddress((void**)&h1, g_h1);
    cudaGetSymbolAddress((void**)&h2, g_h2);
    cudaGetSymbolAddress((void**)&msg, g_msg);
    cudaGetSymbolAddress((void**)&q, g_q);
    cudaGetSymbolAddress((void**)&mk, g_mk);
    cudaGetSymbolAddress((void**)&mv, g_mv);
    cudaGetSymbolAddress((void**)&att, g_att);

    const int gb = N_NODES / 32;  // 512 blocks
    gemm128<1, 1, 1, 0><<<gb, 128>>>(features, W1, b1, nullptr, h1);   // 0
    gemm128<0, 1, 1, 0><<<gb, 128>>>(h1, W2, b2, nullptr, h2);         // 1
    gemm128<0, 1, 1, 1><<<gb, 128>>>(h2, W3, b3, encoder, msg);        // 2
    gemm128<0, 0, 1, 0><<<gb, 128>>>(features, Wq, bq, nullptr, q);    // 3
    gemm128_dual_h<<<gb, 128>>>(msg, Wk, Wv, mk, mv);                  // 4
    attn_kernel<<<N_NODES / 4, 128>>>(distances, sequence, idx,        // 5
                                      q, mk, mv, Wk, bk, Wv, bv, att);
    gemm128<0, 0, 1, 1><<<gb, 128>>>(att, Wo, bo, features, (float*)d_out); // 6
}

// round 8
// speedup vs baseline: 1.4744x; 1.4744x over previous
#include <cuda_runtime.h>
#include <cuda_fp16.h>

#define N_NODES 16384
#define SZ 128
typedef unsigned long long ull;

__device__ __forceinline__ ull ffma2(ull a, ull b, ull c) {
    ull d;
    asm("fma.rn.f32x2 %0, %1, %2, %3;" : "=l"(d) : "l"(a), "l"(b), "l"(c));
    return d;
}
__device__ __forceinline__ ull pack2(float x, float y) {
    ull d;
    asm("mov.b64 %0, {%1, %2};" : "=l"(d) : "f"(x), "f"(y));
    return d;
}
__device__ __forceinline__ float2 unpack2(ull v) {
    float2 r;
    asm("mov.b64 {%0, %1}, %2;" : "=f"(r.x), "=f"(r.y) : "l"(v));
    return r;
}
__device__ __forceinline__ unsigned h2u(__half2 h) { return *(unsigned*)&h; }

// ---------------- scratch ----------------
__device__ float  g_h1[N_NODES * SZ];
__device__ float  g_h2[N_NODES * SZ];
__device__ float  g_msg[N_NODES * SZ];
__device__ float  g_q[N_NODES * SZ];
__device__ __half g_mk[N_NODES * SZ];
__device__ __half g_mv[N_NODES * SZ];
__device__ float  g_att[N_NODES * SZ];

// ---------------- GEMM (R4-proven): BM=64, BN=128, BK=32, 256 thr, 8x4/thr -
template <int RELU_IN, int RELU_OUT, int HAS_BIAS, int HAS_ADD>
__global__ __launch_bounds__(256) void gemm128(
    const float* __restrict__ A, const float* __restrict__ W,
    const float* __restrict__ bias, const float* __restrict__ add,
    float* __restrict__ C)
{
    __shared__ float As[32 * 64];    // [k][row]
    __shared__ float Ws[32 * 128];   // [k][col]
    const int t = threadIdx.x;
    const int tx = t & 31;
    const int ty = t >> 5;
    const int row0 = blockIdx.x * 64;

    float acc[8][4];
#pragma unroll
    for (int r = 0; r < 8; r++)
#pragma unroll
        for (int c = 0; c < 4; c++) acc[r][c] = 0.0f;

    for (int kt = 0; kt < 4; kt++) {
        const int kk0 = kt * 32;
        __syncthreads();
#pragma unroll
        for (int i = 0; i < 2; i++) {
            int f = t + i * 256;
            int r = f >> 3, c4 = f & 7;
            float4 v = *(const float4*)(A + (row0 + r) * 128 + kk0 + c4 * 4);
            if (RELU_IN) {
                v.x = fmaxf(v.x, 0.f); v.y = fmaxf(v.y, 0.f);
                v.z = fmaxf(v.z, 0.f); v.w = fmaxf(v.w, 0.f);
            }
            As[(c4 * 4 + 0) * 64 + r] = v.x;
            As[(c4 * 4 + 1) * 64 + r] = v.y;
            As[(c4 * 4 + 2) * 64 + r] = v.z;
            As[(c4 * 4 + 3) * 64 + r] = v.w;
        }
#pragma unroll
        for (int i = 0; i < 4; i++) {
            int f = t + i * 256;
            int kr = f >> 5, c4 = f & 31;
            *(float4*)(Ws + kr * 128 + c4 * 4) =
                *(const float4*)(W + (kk0 + kr) * 128 + c4 * 4);
        }
        __syncthreads();
#pragma unroll
        for (int kk = 0; kk < 32; kk++) {
            float4 a0 = *(const float4*)(As + kk * 64 + ty * 8);
            float4 a1 = *(const float4*)(As + kk * 64 + ty * 8 + 4);
            float4 w  = *(const float4*)(Ws + kk * 128 + tx * 4);
            float ar[8] = {a0.x, a0.y, a0.z, a0.w, a1.x, a1.y, a1.z, a1.w};
#pragma unroll
            for (int r = 0; r < 8; r++) {
                acc[r][0] += ar[r] * w.x;
                acc[r][1] += ar[r] * w.y;
                acc[r][2] += ar[r] * w.z;
                acc[r][3] += ar[r] * w.w;
            }
        }
    }

    float4 bz = make_float4(0.f, 0.f, 0.f, 0.f);
    if (HAS_BIAS) bz = *(const float4*)(bias + tx * 4);
#pragma unroll
    for (int r = 0; r < 8; r++) {
        int gr = row0 + ty * 8 + r;
        float4 o;
        o.x = acc[r][0] + bz.x;
        o.y = acc[r][1] + bz.y;
        o.z = acc[r][2] + bz.z;
        o.w = acc[r][3] + bz.w;
        if (RELU_OUT) {
            o.x = fmaxf(o.x, 0.f); o.y = fmaxf(o.y, 0.f);
            o.z = fmaxf(o.z, 0.f); o.w = fmaxf(o.w, 0.f);
        }
        if (HAS_ADD) {
            float4 av = *(const float4*)(add + gr * 128 + tx * 4);
            o.x += av.x; o.y += av.y; o.z += av.z; o.w += av.w;
        }
        *(float4*)(C + gr * 128 + tx * 4) = o;
    }
}

// ------- fused h1 & q: h1 = relu(relu(F)@W1+b1), q = F@Wq+bq (F loaded once)
__global__ __launch_bounds__(256) void gemm_h1_q(
    const float* __restrict__ F, const float* __restrict__ W1g,
    const float* __restrict__ b1, const float* __restrict__ Wqg,
    const float* __restrict__ bq, float* __restrict__ H1,
    float* __restrict__ Q)
{
    __shared__ float AsR[32 * 64];   // relu(F), [k][row]
    __shared__ float AsN[32 * 64];   // raw F
    __shared__ float Ws1[32 * 128];
    __shared__ float Ws2[32 * 128];
    const int t = threadIdx.x;
    const int tx = t & 31;
    const int ty = t >> 5;
    const int row0 = blockIdx.x * 64;

    float a1[8][4], a2[8][4];
#pragma unroll
    for (int r = 0; r < 8; r++)
#pragma unroll
        for (int c = 0; c < 4; c++) { a1[r][c] = 0.f; a2[r][c] = 0.f; }

    for (int kt = 0; kt < 4; kt++) {
        const int kk0 = kt * 32;
        __syncthreads();
#pragma unroll
        for (int i = 0; i < 2; i++) {
            int f = t + i * 256;
            int r = f >> 3, c4 = f & 7;
            float4 v = *(const float4*)(F + (row0 + r) * 128 + kk0 + c4 * 4);
            AsN[(c4 * 4 + 0) * 64 + r] = v.x;
            AsN[(c4 * 4 + 1) * 64 + r] = v.y;
            AsN[(c4 * 4 + 2) * 64 + r] = v.z;
            AsN[(c4 * 4 + 3) * 64 + r] = v.w;
            AsR[(c4 * 4 + 0) * 64 + r] = fmaxf(v.x, 0.f);
            AsR[(c4 * 4 + 1) * 64 + r] = fmaxf(v.y, 0.f);
            AsR[(c4 * 4 + 2) * 64 + r] = fmaxf(v.z, 0.f);
            AsR[(c4 * 4 + 3) * 64 + r] = fmaxf(v.w, 0.f);
        }
#pragma unroll
        for (int i = 0; i < 4; i++) {
            int f = t + i * 256;
            int kr = f >> 5, c4 = f & 31;
            *(float4*)(Ws1 + kr * 128 + c4 * 4) =
                *(const float4*)(W1g + (kk0 + kr) * 128 + c4 * 4);
            *(float4*)(Ws2 + kr * 128 + c4 * 4) =
                *(const float4*)(Wqg + (kk0 + kr) * 128 + c4 * 4);
        }
        __syncthreads();
#pragma unroll
        for (int kk = 0; kk < 32; kk++) {
            float4 r0 = *(const float4*)(AsR + kk * 64 + ty * 8);
            float4 r1 = *(const float4*)(AsR + kk * 64 + ty * 8 + 4);
            float4 n0 = *(const float4*)(AsN + kk * 64 + ty * 8);
            float4 n1 = *(const float4*)(AsN + kk * 64 + ty * 8 + 4);
            float4 w1 = *(const float4*)(Ws1 + kk * 128 + tx * 4);
            float4 w2 = *(const float4*)(Ws2 + kk * 128 + tx * 4);
            float rr[8] = {r0.x, r0.y, r0.z, r0.w, r1.x, r1.y, r1.z, r1.w};
            float nn[8] = {n0.x, n0.y, n0.z, n0.w, n1.x, n1.y, n1.z, n1.w};
#pragma unroll
            for (int r = 0; r < 8; r++) {
                a1[r][0] += rr[r] * w1.x; a1[r][1] += rr[r] * w1.y;
                a1[r][2] += rr[r] * w1.z; a1[r][3] += rr[r] * w1.w;
                a2[r][0] += nn[r] * w2.x; a2[r][1] += nn[r] * w2.y;
                a2[r][2] += nn[r] * w2.z; a2[r][3] += nn[r] * w2.w;
            }
        }
    }

    float4 bz1 = *(const float4*)(b1 + tx * 4);
    float4 bzq = *(const float4*)(bq + tx * 4);
#pragma unroll
    for (int r = 0; r < 8; r++) {
        int gr = row0 + ty * 8 + r;
        float4 o1 = make_float4(fmaxf(a1[r][0] + bz1.x, 0.f),
                                fmaxf(a1[r][1] + bz1.y, 0.f),
                                fmaxf(a1[r][2] + bz1.z, 0.f),
                                fmaxf(a1[r][3] + bz1.w, 0.f));
        float4 oq = make_float4(a2[r][0] + bzq.x, a2[r][1] + bzq.y,
                                a2[r][2] + bzq.z, a2[r][3] + bzq.w);
        *(float4*)(H1 + gr * 128 + tx * 4) = o1;
        *(float4*)(Q + gr * 128 + tx * 4) = oq;
    }
}

// ---------------- dual GEMM -> fp16: mk = A@Wk[:128], mv = A@Wv[:128] ------
__global__ __launch_bounds__(256) void gemm128_dual_h(
    const float* __restrict__ A, const float* __restrict__ W1g,
    const float* __restrict__ W2g, __half* __restrict__ C1,
    __half* __restrict__ C2)
{
    __shared__ float As[32 * 64];
    __shared__ float Ws1[32 * 128];
    __shared__ float Ws2[32 * 128];
    const int t = threadIdx.x;
    const int tx = t & 31;
    const int ty = t >> 5;
    const int row0 = blockIdx.x * 64;

    float a1[8][4], a2[8][4];
#pragma unroll
    for (int r = 0; r < 8; r++)
#pragma unroll
        for (int c = 0; c < 4; c++) { a1[r][c] = 0.f; a2[r][c] = 0.f; }

    for (int kt = 0; kt < 4; kt++) {
        const int kk0 = kt * 32;
        __syncthreads();
#pragma unroll
        for (int i = 0; i < 2; i++) {
            int f = t + i * 256;
            int r = f >> 3, c4 = f & 7;
            float4 v = *(const float4*)(A + (row0 + r) * 128 + kk0 + c4 * 4);
            As[(c4 * 4 + 0) * 64 + r] = v.x;
            As[(c4 * 4 + 1) * 64 + r] = v.y;
            As[(c4 * 4 + 2) * 64 + r] = v.z;
            As[(c4 * 4 + 3) * 64 + r] = v.w;
        }
#pragma unroll
        for (int i = 0; i < 4; i++) {
            int f = t + i * 256;
            int kr = f >> 5, c4 = f & 31;
            *(float4*)(Ws1 + kr * 128 + c4 * 4) =
                *(const float4*)(W1g + (kk0 + kr) * 128 + c4 * 4);
            *(float4*)(Ws2 + kr * 128 + c4 * 4) =
                *(const float4*)(W2g + (kk0 + kr) * 128 + c4 * 4);
        }
        __syncthreads();
#pragma unroll
        for (int kk = 0; kk < 32; kk++) {
            float4 a0 = *(const float4*)(As + kk * 64 + ty * 8);
            float4 a1r = *(const float4*)(As + kk * 64 + ty * 8 + 4);
            float4 w1 = *(const float4*)(Ws1 + kk * 128 + tx * 4);
            float4 w2 = *(const float4*)(Ws2 + kk * 128 + tx * 4);
            float ar[8] = {a0.x, a0.y, a0.z, a0.w, a1r.x, a1r.y, a1r.z, a1r.w};
#pragma unroll
            for (int r = 0; r < 8; r++) {
                a1[r][0] += ar[r] * w1.x; a1[r][1] += ar[r] * w1.y;
                a1[r][2] += ar[r] * w1.z; a1[r][3] += ar[r] * w1.w;
                a2[r][0] += ar[r] * w2.x; a2[r][1] += ar[r] * w2.y;
                a2[r][2] += ar[r] * w2.z; a2[r][3] += ar[r] * w2.w;
            }
        }
    }
#pragma unroll
    for (int r = 0; r < 8; r++) {
        int gr = row0 + ty * 8 + r;
        uint2 o1, o2;
        o1.x = h2u(__float22half2_rn(make_float2(a1[r][0], a1[r][1])));
        o1.y = h2u(__float22half2_rn(make_float2(a1[r][2], a1[r][3])));
        o2.x = h2u(__float22half2_rn(make_float2(a2[r][0], a2[r][1])));
        o2.y = h2u(__float22half2_rn(make_float2(a2[r][2], a2[r][3])));
        *(uint2*)(C1 + (long)gr * 128 + tx * 4) = o1;
        *(uint2*)(C2 + (long)gr * 128 + tx * 4) = o2;
    }
}

// ---------------- attention: 1 warp/node, fp16 staging, 8.1KB smem/warp ----
struct __align__(16) WarpSmem {
    __half dist[32 * 36];  // [k][d] pad-36 halves (72B rows, 8B-aligned)
    __half seq[32 * 20];   // [k][s] pad-20 halves (40B rows)
    float ud_t[32 * 8];    // [d][h]  (transposed fold tables)
    float us_t[16 * 8];    // [s][h]
    float c0[8];
    float lgk[32 * 10];    // [k][h] pad-10
    float sd[8 * 32];
    float ss[8 * 16];
    int   jb[32];
};

__global__ __launch_bounds__(128, 7) void attn_kernel(
    const float* __restrict__ dist_g, const float* __restrict__ seq_g,
    const int* __restrict__ idx, const float* __restrict__ qg,
    const __half* __restrict__ mkh, const __half* __restrict__ mvh,
    const float* __restrict__ Wk, const float* __restrict__ bk,
    const float* __restrict__ Wv, const float* __restrict__ bv,
    float* __restrict__ att_out)
{
    __shared__ WarpSmem S[4];
    const int lane = threadIdx.x & 31;
    const int w = threadIdx.x >> 5;
    WarpSmem& s = S[w];
    const int n = blockIdx.x * 4 + w;

    // ---- Phase A: coalesced staging (fp32 global -> fp16 smem)
    const float4 qv = ((const float4*)(qg + (long)n * 128))[lane];
    s.jb[lane] = idx[n * 32 + lane];
    {
        const float4* dg = (const float4*)(dist_g + (long)n * 1024);
#pragma unroll
        for (int it = 0; it < 8; it++) {
            int i4 = it * 32 + lane;
            float4 v = dg[i4];
            uint2 h;
            h.x = h2u(__float22half2_rn(make_float2(v.x, v.y)));
            h.y = h2u(__float22half2_rn(make_float2(v.z, v.w)));
            *(uint2*)(s.dist + (i4 >> 3) * 36 + (i4 & 7) * 4) = h;
        }
        const float4* sg = (const float4*)(seq_g + (long)n * 512);
#pragma unroll
        for (int it = 0; it < 4; it++) {
            int i4 = it * 32 + lane;
            float4 v = sg[i4];
            uint2 h;
            h.x = h2u(__float22half2_rn(make_float2(v.x, v.y)));
            h.y = h2u(__float22half2_rn(make_float2(v.z, v.w)));
            *(uint2*)(s.seq + (i4 >> 2) * 20 + (i4 & 3) * 4) = h;
        }
    }
    __syncwarp();

    // ---- Phase B: folds into TRANSPOSED tables ud_t[d][h], us_t[s][h]
    const int h4 = lane >> 2;
#pragma unroll 8
    for (int r = 0; r < 48; r++) {
        float4 wv = *(const float4*)(Wk + (long)(128 + r) * 128 + lane * 4);
        float p = wv.x * qv.x + wv.y * qv.y + wv.z * qv.z + wv.w * qv.w;
        p += __shfl_xor_sync(~0u, p, 1);
        p += __shfl_xor_sync(~0u, p, 2);
        if ((lane & 3) == 0) {
            if (r < 32) s.ud_t[r * 8 + h4] = p;
            else        s.us_t[(r - 32) * 8 + h4] = p;
        }
    }
    {
        float4 wv = *(const float4*)(bk + lane * 4);
        float p = wv.x * qv.x + wv.y * qv.y + wv.z * qv.z + wv.w * qv.w;
        p += __shfl_xor_sync(~0u, p, 1);
        p += __shfl_xor_sync(~0u, p, 2);
        if ((lane & 3) == 0) s.c0[h4] = p;
    }
    __syncwarp();

    // ---- Phase C1: q . mk[jb[k]] — fp16 rows, 8B/lane coalesced
#pragma unroll 8
    for (int k = 0; k < 32; k++) {
        int j = s.jb[k];
        uint2 mr = *(const uint2*)(mkh + (long)j * 128 + lane * 4);
        float2 f0 = __half22float2(*(__half2*)&mr.x);
        float2 f1 = __half22float2(*(__half2*)&mr.y);
        float p = f0.x * qv.x + f0.y * qv.y + f1.x * qv.z + f1.y * qv.w;
        p += __shfl_xor_sync(~0u, p, 1);
        p += __shfl_xor_sync(~0u, p, 2);
        if ((lane & 3) == 0) s.lgk[k * 10 + h4] = p;
    }
    __syncwarp();

    // ---- Phase C2: logits via head-pair accumulators (4 ull regs) + softmax
    float lg[8];
    {
        ull acc01 = 0ull, acc23 = 0ull, acc45 = 0ull, acc67 = 0ull;
        const __half* drow = s.dist + lane * 36;
#pragma unroll
        for (int i = 0; i < 8; i++) {
            uint2 hv = *(const uint2*)(drow + i * 4);
            float2 f0 = __half22float2(*(__half2*)&hv.x);
            float2 f1 = __half22float2(*(__half2*)&hv.y);
            float dv[4] = {f0.x, f0.y, f1.x, f1.y};
#pragma unroll
            for (int e = 0; e < 4; e++) {
                int d = i * 4 + e;
                ull dv2 = pack2(dv[e], dv[e]);
                const ull* u = (const ull*)(s.ud_t + d * 8);
                acc01 = ffma2(u[0], dv2, acc01);
                acc23 = ffma2(u[1], dv2, acc23);
                acc45 = ffma2(u[2], dv2, acc45);
                acc67 = ffma2(u[3], dv2, acc67);
            }
        }
        const __half* srow = s.seq + lane * 20;
#pragma unroll
        for (int i = 0; i < 4; i++) {
            uint2 hv = *(const uint2*)(srow + i * 4);
            float2 f0 = __half22float2(*(__half2*)&hv.x);
            float2 f1 = __half22float2(*(__half2*)&hv.y);
            float sv[4] = {f0.x, f0.y, f1.x, f1.y};
#pragma unroll
            for (int e = 0; e < 4; e++) {
                int si = i * 4 + e;
                ull sv2 = pack2(sv[e], sv[e]);
                const ull* u = (const ull*)(s.us_t + si * 8);
                acc01 = ffma2(u[0], sv2, acc01);
                acc23 = ffma2(u[1], sv2, acc23);
                acc45 = ffma2(u[2], sv2, acc45);
                acc67 = ffma2(u[3], sv2, acc67);
            }
        }
        float2 p01 = unpack2(acc01), p23 = unpack2(acc23);
        float2 p45 = unpack2(acc45), p67 = unpack2(acc67);
        float pa[8] = {p01.x, p01.y, p23.x, p23.y, p45.x, p45.y, p67.x, p67.y};
#pragma unroll
        for (int h = 0; h < 8; h++)
            lg[h] = 0.25f * (s.lgk[lane * 10 + h] + pa[h] + s.c0[h]);
    }
#pragma unroll
    for (int h = 0; h < 8; h++) {
        float m = lg[h];
#pragma unroll
        for (int o = 16; o > 0; o >>= 1) m = fmaxf(m, __shfl_xor_sync(~0u, m, o));
        float e = __expf(lg[h] - m);
        float sm = e;
#pragma unroll
        for (int o = 16; o > 0; o >>= 1) sm += __shfl_xor_sync(~0u, sm, o);
        s.lgk[lane * 10 + h] = e / sm;
    }
    __syncwarp();

    // ---- Phase D: weighted sums — fp16 mv gather, 8B/lane
    const int sidx = lane & 15;
    float4 acc = make_float4(0.f, 0.f, 0.f, 0.f);
    ull sdl2[4] = {0ull, 0ull, 0ull, 0ull};
    float ssl[4] = {0.f, 0.f, 0.f, 0.f};
#pragma unroll 4
    for (int k = 0; k < 32; k++) {
        int j = s.jb[k];
        float a = s.lgk[k * 10 + h4];
        uint2 mr = *(const uint2*)(mvh + (long)j * 128 + lane * 4);
        float2 f0 = __half22float2(*(__half2*)&mr.x);
        float2 f1 = __half22float2(*(__half2*)&mr.y);
        acc.x += a * f0.x; acc.y += a * f0.y;
        acc.z += a * f1.x; acc.w += a * f1.y;
        float dv = __half2float(s.dist[k * 36 + lane]);
        ull dv2 = pack2(dv, dv);
        const ull* ap = (const ull*)(s.lgk + k * 10);
#pragma unroll
        for (int r = 0; r < 4; r++) sdl2[r] = ffma2(ap[r], dv2, sdl2[r]);
        float sv = __half2float(s.seq[k * 20 + sidx]);
#pragma unroll
        for (int r = 0; r < 4; r++) {
            int h2 = (lane >> 4) + 2 * r;
            ssl[r] += s.lgk[k * 10 + h2] * sv;
        }
    }
#pragma unroll
    for (int r = 0; r < 4; r++) {
        float2 p = unpack2(sdl2[r]);
        s.sd[(2 * r) * 32 + lane] = p.x;
        s.sd[(2 * r + 1) * 32 + lane] = p.y;
    }
#pragma unroll
    for (int r = 0; r < 4; r++) s.ss[lane + 32 * r] = ssl[r];
    __syncwarp();

    // ---- Phase D2: outv = acc + sd @ WvD + ss @ WvS + bv (f32x2)
    {
        const int i0 = lane * 4;
        float4 bvv = *(const float4*)(bv + i0);
        ull o01 = pack2(bvv.x + acc.x, bvv.y + acc.y);
        ull o23 = pack2(bvv.z + acc.z, bvv.w + acc.w);
#pragma unroll 8
        for (int d = 0; d < 32; d++) {
            float sdv = s.sd[h4 * 32 + d];
            ull s2 = pack2(sdv, sdv);
            ulonglong2 wv = *(const ulonglong2*)(Wv + (long)(128 + d) * 128 + i0);
            o01 = ffma2(wv.x, s2, o01);
            o23 = ffma2(wv.y, s2, o23);
        }
#pragma unroll 8
        for (int j = 0; j < 16; j++) {
            float ssv = s.ss[h4 * 16 + j];
            ull s2 = pack2(ssv, ssv);
            ulonglong2 wv = *(const ulonglong2*)(Wv + (long)(160 + j) * 128 + i0);
            o01 = ffma2(wv.x, s2, o01);
            o23 = ffma2(wv.y, s2, o23);
        }
        float2 p0 = unpack2(o01), p1 = unpack2(o23);
        *(float4*)(att_out + (long)n * 128 + i0) =
            make_float4(p0.x, p0.y, p1.x, p1.y);
    }
}

// ---------------- launch ----------------
extern "C" void kernel_launch(void* const* d_in, const int* in_sizes, int n_in,
                              void* d_out, int out_size)
{
    const float* features = (const float*)d_in[0];
    const float* distances = (const float*)d_in[1];
    const float* sequence = (const float*)d_in[2];
    const float* encoder = (const float*)d_in[3];
    const int*   idx = (const int*)d_in[4];
    const float* W1 = (const float*)d_in[5];
    const float* b1 = (const float*)d_in[6];
    const float* W2 = (const float*)d_in[7];
    const float* b2 = (const float*)d_in[8];
    const float* W3 = (const float*)d_in[9];
    const float* b3 = (const float*)d_in[10];
    const float* Wq = (const float*)d_in[11];
    const float* bq = (const float*)d_in[12];
    const float* Wk = (const float*)d_in[13];
    const float* bk = (const float*)d_in[14];
    const float* Wv = (const float*)d_in[15];
    const float* bv = (const float*)d_in[16];
    const float* Wo = (const float*)d_in[17];
    const float* bo = (const float*)d_in[18];

    float *h1, *h2, *msg, *q, *att;
    __half *mk, *mv;
    cudaGetSymbolAddress((void**)&h1, g_h1);
    cudaGetSymbolAddress((void**)&h2, g_h2);
    cudaGetSymbolAddress((void**)&msg, g_msg);
    cudaGetSymbolAddress((void**)&q, g_q);
    cudaGetSymbolAddress((void**)&mk, g_mk);
    cudaGetSymbolAddress((void**)&mv, g_mv);
    cudaGetSymbolAddress((void**)&att, g_att);

    const int gb = N_NODES / 64;  // 256 blocks
    gemm_h1_q<<<gb, 256>>>(features, W1, b1, Wq, bq, h1, q);           // 0
    gemm128<0, 1, 1, 0><<<gb, 256>>>(h1, W2, b2, nullptr, h2);         // 1
    gemm128<0, 1, 1, 1><<<gb, 256>>>(h2, W3, b3, encoder, msg);        // 2
    gemm128_dual_h<<<gb, 256>>>(msg, Wk, Wv, mk, mv);                  // 3
    attn_kernel<<<N_NODES / 4, 128>>>(distances, sequence, idx,        // 4
                                      q, mk, mv, Wk, bk, Wv, bv, att);
    gemm128<0, 0, 1, 1><<<gb, 256>>>(att, Wo, bo, features, (float*)d_out); // 5
}